// round 4
// baseline (speedup 1.0000x reference)
#include <cstdint>
#include <cuda_runtime.h>
#include <cuda_bf16.h>
#include <mma.h>

using namespace nvcuda;

#define BB 128
#define SS 256
#define DD 512
#define HH 1024
#define NCC 128
#define NCTA_REC 128

// ---------------- device scratch ----------------
__device__ float          g_P[(size_t)SS * BB * 4096];     // input-side preacts (no bias)
__device__ __nv_bfloat16  g_h2[2][BB * HH];                // double-buffered hidden state
__device__ float          g_hf[BB * HH];                   // final hidden state
__device__ unsigned       g_flag[NCTA_REC * 32];           // per-CTA arrival flags (128B-line padded)
__device__ unsigned       g_gen = 0;                       // barrier generation (monotonic)
__device__ __nv_bfloat16  g_embb[(NCC + 1) * DD];          // bf16 embedding
__device__ __nv_bfloat16  g_Wxb[4][(size_t)DD * HH];       // bf16 input weights

__device__ __forceinline__ float sigm(float v) { return 1.0f / (1.0f + expf(-v)); }

__device__ __forceinline__ void cp16(unsigned int dst, const void* src) {
    asm volatile("cp.async.cg.shared.global [%0], [%1], 16;\n" :: "r"(dst), "l"(src));
}
__device__ __forceinline__ void cp_commit() { asm volatile("cp.async.commit_group;\n"); }
template <int N> __device__ __forceinline__ void cp_wait() {
    asm volatile("cp.async.wait_group %0;\n" :: "n"(N));
}

// Tree barrier: parallel flag stores (no atomic contention), CTA0 aggregates,
// single-word release. Generation seeded from persistent g_gen => replay-safe.
__device__ __forceinline__ void gridbar(unsigned& gen)
{
    const unsigned next = gen + 1u;
    __syncthreads();
    if (threadIdx.x == 0) {
        __threadfence();
        *(volatile unsigned*)&g_flag[blockIdx.x * 32] = next;   // arrive
    }
    if (blockIdx.x == 0) {
        if (threadIdx.x < NCTA_REC) {
            volatile unsigned* f = &g_flag[threadIdx.x * 32];
            while (*f != next) { }
        }
        __syncthreads();
        if (threadIdx.x == 0) {
            __threadfence();
            *(volatile unsigned*)&g_gen = next;                 // release
        }
    } else if (threadIdx.x == 0) {
        volatile unsigned* g = &g_gen;
        while (*g != next) { }
    }
    __syncthreads();
    __threadfence();   // acquire
    gen = next;
}

// ======================================================================
// Kernel 0: one-time f32 -> bf16 conversion of emb and the 4 input weights
// ======================================================================
__global__ __launch_bounds__(256) void k_convert(
    const float* __restrict__ emb,
    const float* __restrict__ W0, const float* __restrict__ W1,
    const float* __restrict__ W2, const float* __restrict__ W3)
{
    const float* Wsrc[4] = { W0, W1, W2, W3 };
    size_t tid    = (size_t)blockIdx.x * blockDim.x + threadIdx.x;
    size_t stride = (size_t)gridDim.x * blockDim.x;
    const size_t nW4 = (size_t)DD * HH / 4;
    for (size_t e = tid; e < 4 * nW4; e += stride) {
        int g = (int)(e / nW4);
        size_t o = (e % nW4) * 4;
        float4 v = *(const float4*)(Wsrc[g] + o);
        __nv_bfloat16* d = &g_Wxb[g][o];
        d[0] = __float2bfloat16(v.x); d[1] = __float2bfloat16(v.y);
        d[2] = __float2bfloat16(v.z); d[3] = __float2bfloat16(v.w);
    }
    const size_t nE4 = (size_t)(NCC + 1) * DD / 4;
    for (size_t e = tid; e < nE4; e += stride) {
        float4 v = *(const float4*)(emb + e * 4);
        __nv_bfloat16* d = &g_embb[e * 4];
        d[0] = __float2bfloat16(v.x); d[1] = __float2bfloat16(v.y);
        d[2] = __float2bfloat16(v.z); d[3] = __float2bfloat16(v.w);
    }
}

// ======================================================================
// Kernel 1: input projections (bf16 wmma, 3-stage cp.async, dynamic SMEM)
// ======================================================================
#define AS_LD 56
#define BS_LD 152
#define K1_STG 3

__global__ __launch_bounds__(256) void k_input_proj(const int* __restrict__ x)
{
    extern __shared__ __align__(16) unsigned char dyn1[];
    __nv_bfloat16* As = (__nv_bfloat16*)dyn1;                       // [3][128*AS_LD]
    __nv_bfloat16* Bs = As + K1_STG * 128 * AS_LD;                  // [3][32*BS_LD]
    __shared__ int rowidx[128];

    const int t = threadIdx.x, w = t >> 5;
    const int tn = blockIdx.x, tm = blockIdx.y;
    const int n0 = tn * 128, gate = n0 >> 10, h0 = n0 & 1023;
    const __nv_bfloat16* Wb = g_Wxb[gate];

    if (t < 128) {
        int m = tm * 128 + t;
        int s = m >> 7, b = m & 127;
        rowidx[t] = x[b * SS + s];
    }
    __syncthreads();

    auto issue = [&](int it, int buf) {
        int kt = it * 32;
        unsigned int Aa = (unsigned int)__cvta_generic_to_shared(As + buf * 128 * AS_LD);
        unsigned int Ba = (unsigned int)__cvta_generic_to_shared(Bs + buf * 32 * BS_LD);
#pragma unroll
        for (int i = 0; i < 2; i++) {                 // A: 128 rows x 32 cols
            int e = t + i * 256, r = e >> 2, seg = e & 3;
            cp16(Aa + (r * AS_LD + seg * 8) * 2,
                 g_embb + (size_t)rowidx[r] * DD + kt + seg * 8);
        }
#pragma unroll
        for (int i = 0; i < 2; i++) {                 // B: 32 rows x 128 cols
            int e = t + i * 256, r = e >> 4, seg = e & 15;
            cp16(Ba + (r * BS_LD + seg * 8) * 2,
                 Wb + (size_t)(kt + r) * HH + h0 + seg * 8);
        }
    };

    wmma::fragment<wmma::accumulator, 16, 16, 16, float> acc[8];
#pragma unroll
    for (int i = 0; i < 8; i++) wmma::fill_fragment(acc[i], 0.0f);

    issue(0, 0); cp_commit();
    issue(1, 1); cp_commit();
    issue(2, 2); cp_commit();

    for (int it = 0; it < 16; it++) {
        const int buf = it % K1_STG;
        cp_wait<2>();
        __syncthreads();
        const __nv_bfloat16* A = As + buf * 128 * AS_LD;
        const __nv_bfloat16* B = Bs + buf * 32 * BS_LD;
#pragma unroll
        for (int ks = 0; ks < 2; ks++) {
            wmma::fragment<wmma::matrix_a, 16, 16, 16, __nv_bfloat16, wmma::row_major> af;
            wmma::load_matrix_sync(af, A + (w * 16) * AS_LD + ks * 16, AS_LD);
#pragma unroll
            for (int nb = 0; nb < 8; nb++) {
                wmma::fragment<wmma::matrix_b, 16, 16, 16, __nv_bfloat16, wmma::row_major> bfr;
                wmma::load_matrix_sync(bfr, B + (ks * 16) * BS_LD + nb * 16, BS_LD);
                wmma::mma_sync(acc[nb], af, bfr, acc[nb]);
            }
        }
        __syncthreads();
        if (it + K1_STG < 16) issue(it + K1_STG, buf);
        cp_commit();
    }

    size_t base = (size_t)(tm * 128 + w * 16) * 4096 + n0;
#pragma unroll
    for (int nb = 0; nb < 8; nb++)
        wmma::store_matrix_sync(g_P + base + nb * 16, acc[nb], 4096, wmma::mem_row_major);
}

// ======================================================================
// Kernel 2: persistent recurrent scan. 128 CTAs x 8 hidden units.
// 3-stage cp.async h staging; weights resident in SMEM; flag-tree barrier.
// ======================================================================
#define WS_LD 1032
#define HA_LD 152
#define K2_STG 3

__global__ void __launch_bounds__(256, 1) k_recur(
    const int*   __restrict__ x,
    const float* __restrict__ Wfh, const float* __restrict__ Wih,
    const float* __restrict__ Wgh, const float* __restrict__ Woh,
    const float* __restrict__ bfp, const float* __restrict__ bip,
    const float* __restrict__ bgp, const float* __restrict__ bop)
{
    extern __shared__ __align__(16) unsigned char dyn[];
    __nv_bfloat16* Ws = (__nv_bfloat16*)dyn;               // [32][WS_LD] col-major
    __nv_bfloat16* hA = Ws + 32 * WS_LD;                   // [3][128*HA_LD]
    float* Sg = (float*)(hA + K2_STG * 128 * HA_LD);       // [128][32]
    float* Cs = Sg + 128 * 32;                             // [128][8]

    const int t = threadIdx.x, w = t >> 5;
    const int c = blockIdx.x, u0 = c * 8;
    const float* Wg[4] = { Wfh, Wih, Wgh, Woh };

    for (int e = t; e < 32 * 1024; e += 256) {
        int k = e >> 5, col = e & 31, g = col >> 3, j = col & 7;
        Ws[col * WS_LD + k] = __float2bfloat16(Wg[g][(size_t)k * HH + u0 + j]);
    }
    for (int e = t; e < 1024; e += 256) {
        int b = e >> 3, j = e & 7;
        g_h2[0][b * HH + u0 + j] = __float2bfloat16(0.0f);
        Cs[b * 8 + j] = 0.0f;
    }
    const int jj = t & 7;
    const float bias0 = bfp[u0 + jj], bias1 = bip[u0 + jj];
    const float bias2 = bgp[u0 + jj], bias3 = bop[u0 + jj];

    unsigned int hAa[K2_STG];
#pragma unroll
    for (int i = 0; i < K2_STG; i++)
        hAa[i] = (unsigned int)__cvta_generic_to_shared(hA + i * 128 * HA_LD);

    unsigned gen = *(volatile unsigned*)&g_gen;   // stable between launches
    gridbar(gen);   // zeros visible everywhere

    for (int s = 0; s < SS; s++) {
        const __nv_bfloat16* hsrc = g_h2[s & 1];
        __nv_bfloat16*       hdst = g_h2[(s + 1) & 1];

        auto issueh = [&](int kc, int buf) {
#pragma unroll
            for (int i = 0; i < 8; i++) {
                int e = t + i * 256, r = e >> 4, seg = e & 15;
                cp16(hAa[buf] + (r * HA_LD + seg * 8) * 2,
                     hsrc + r * HH + kc * 128 + seg * 8);
            }
        };

        issueh(0, 0); cp_commit();
        issueh(1, 1); cp_commit();
        issueh(2, 2); cp_commit();

        // prefetch input-side preacts + reset mask (independent of h)
        float pf[4][4]; int xr[4];
#pragma unroll
        for (int i = 0; i < 4; i++) {
            int e = t + i * 256, b = e >> 3, j = e & 7;
            const float* Pb = g_P + ((size_t)(s * BB + b)) * 4096 + (u0 + j);
            pf[i][0] = Pb[0];    pf[i][1] = Pb[1024];
            pf[i][2] = Pb[2048]; pf[i][3] = Pb[3072];
            xr[i] = x[b * SS + s];
        }

        wmma::fragment<wmma::accumulator, 16, 16, 16, float> acc[2];
        wmma::fill_fragment(acc[0], 0.0f);
        wmma::fill_fragment(acc[1], 0.0f);

        for (int kc = 0; kc < 8; kc++) {
            const int buf = kc % K2_STG;
            cp_wait<2>();
            __syncthreads();
            const __nv_bfloat16* A = hA + buf * 128 * HA_LD;
#pragma unroll
            for (int ks = 0; ks < 8; ks++) {
                wmma::fragment<wmma::matrix_a, 16, 16, 16, __nv_bfloat16, wmma::row_major> af;
                wmma::load_matrix_sync(af, A + (w * 16) * HA_LD + ks * 16, HA_LD);
#pragma unroll
                for (int nb = 0; nb < 2; nb++) {
                    wmma::fragment<wmma::matrix_b, 16, 16, 16, __nv_bfloat16, wmma::col_major> bfr;
                    wmma::load_matrix_sync(bfr, Ws + (nb * 16) * WS_LD + kc * 128 + ks * 16, WS_LD);
                    wmma::mma_sync(acc[nb], af, bfr, acc[nb]);
                }
            }
            __syncthreads();
            if (kc + K2_STG < 8) issueh(kc + K2_STG, buf);
            cp_commit();
        }

        wmma::store_matrix_sync(Sg + (w * 16) * 32 + 0,  acc[0], 32, wmma::mem_row_major);
        wmma::store_matrix_sync(Sg + (w * 16) * 32 + 16, acc[1], 32, wmma::mem_row_major);
        __syncthreads();

#pragma unroll
        for (int i = 0; i < 4; i++) {
            int e = t + i * 256, b = e >> 3, j = e & 7, u = u0 + j;
            float f  = sigm(pf[i][0] + bias0 + Sg[b * 32 +      j]);
            float ii = sigm(pf[i][1] + bias1 + Sg[b * 32 +  8 + j]);
            float gg = sigm(pf[i][2] + bias2 + Sg[b * 32 + 16 + j]);
            float oo = sigm(pf[i][3] + bias3 + Sg[b * 32 + 24 + j]);
            float r  = (xr[i] > 0) ? 1.0f : 0.0f;
            float C  = (gg * ii + Cs[b * 8 + j] * f) * r;
            Cs[b * 8 + j] = C;
            float h = oo * tanhf(C);
            hdst[b * HH + u] = __float2bfloat16(h);
            if (s == SS - 1) g_hf[b * HH + u] = h;
        }

        if (s < SS - 1) gridbar(gen);
    }
}

// ======================================================================
// Kernel 3: logits + log_softmax.  256 thr: split-K x2, 4 independent accums.
// ======================================================================
__global__ __launch_bounds__(256) void k_final(
    const float* __restrict__ Wph, const float* __restrict__ bp,
    float* __restrict__ out)
{
    __shared__ float h[HH];
    __shared__ float part[NCC];
    __shared__ float red[NCC];
    const int b = blockIdx.x, t = threadIdx.x;
    const int cls = t & 127, half = t >> 7;

    for (int i = t; i < HH; i += 256) h[i] = g_hf[b * HH + i];
    __syncthreads();

    const float* W = Wph + (size_t)(half * 512) * NCC + cls;
    const float* hh = h + half * 512;
    float a0 = 0.f, a1 = 0.f, a2 = 0.f, a3 = 0.f;
#pragma unroll 8
    for (int k = 0; k < 512; k += 4) {
        a0 += hh[k + 0] * W[(size_t)(k + 0) * NCC];
        a1 += hh[k + 1] * W[(size_t)(k + 1) * NCC];
        a2 += hh[k + 2] * W[(size_t)(k + 2) * NCC];
        a3 += hh[k + 3] * W[(size_t)(k + 3) * NCC];
    }
    float p = (a0 + a1) + (a2 + a3);
    if (half) part[cls] = p;
    __syncthreads();

    if (half == 0) p += part[cls] + bp[cls];

    if (t < 128) red[t] = p;
    __syncthreads();
    for (int off = 64; off; off >>= 1) {
        if (t < off) red[t] = fmaxf(red[t], red[t + off]);
        __syncthreads();
    }
    float m = red[0]; __syncthreads();
    if (t < 128) red[t] = expf(p - m);
    __syncthreads();
    for (int off = 64; off; off >>= 1) {
        if (t < off) red[t] += red[t + off];
        __syncthreads();
    }
    if (t < 128) {
        float lse = m + logf(red[0]);
        out[b * NCC + t] = p - lse;
    }
}

// ======================================================================
extern "C" void kernel_launch(void* const* d_in, const int* in_sizes, int n_in,
                              void* d_out, int out_size)
{
    const int*   x   = (const int*)  d_in[0];
    const float* emb = (const float*)d_in[1];
    const float* Wfx = (const float*)d_in[2];
    const float* Wfh = (const float*)d_in[3];
    const float* bf  = (const float*)d_in[4];
    const float* Wix = (const float*)d_in[5];
    const float* Wih = (const float*)d_in[6];
    const float* bi  = (const float*)d_in[7];
    const float* Wgx = (const float*)d_in[8];
    const float* Wgh = (const float*)d_in[9];
    const float* bg  = (const float*)d_in[10];
    const float* Wox = (const float*)d_in[11];
    const float* Woh = (const float*)d_in[12];
    const float* bo  = (const float*)d_in[13];
    const float* Wph = (const float*)d_in[14];
    const float* bp  = (const float*)d_in[15];
    float* out = (float*)d_out;

    const int smem1 = K1_STG * (128 * AS_LD + 32 * BS_LD) * 2;                      // 72,192
    const int smem2 = 32 * WS_LD * 2 + K2_STG * 128 * HA_LD * 2 + 128 * 32 * 4 + 128 * 8 * 4; // 203,264
    static bool attr_set = false;
    if (!attr_set) {
        cudaFuncSetAttribute(k_input_proj, cudaFuncAttributeMaxDynamicSharedMemorySize, smem1);
        cudaFuncSetAttribute(k_recur,      cudaFuncAttributeMaxDynamicSharedMemorySize, smem2);
        attr_set = true;
    }

    // 0) bf16 pre-conversion
    k_convert<<<512, 256>>>(emb, Wfx, Wix, Wgx, Wox);

    // 1) input-side projections
    dim3 g1(4096 / 128, (SS * BB) / 128);
    k_input_proj<<<g1, 256, smem1>>>(x);

    // 2) persistent recurrent scan
    k_recur<<<NCTA_REC, 256, smem2>>>(x, Wfh, Wih, Wgh, Woh, bf, bi, bg, bo);

    // 3) final projection + log_softmax
    k_final<<<BB, 256>>>(Wph, bp, out);
}

// round 5
// speedup vs baseline: 1.4375x; 1.4375x over previous
#include <cstdint>
#include <cuda_runtime.h>
#include <cuda_bf16.h>
#include <mma.h>

using namespace nvcuda;

#define BB 128
#define SS 256
#define DD 512
#define HH 1024
#define NCC 128
#define NCTA_REC 128

// ---------------- device scratch ----------------
__device__ float          g_P[(size_t)SS * BB * 4096];      // input-side preacts (no bias)
__device__ __align__(128) unsigned char g_hT2[2][HH * 256]; // transposed+swizzled h: [u][b] bf16, 256B/row
__device__ float          g_hf[BB * HH];                    // final hidden state
__device__ unsigned       g_cnt = 0;
__device__ unsigned       g_gen = 0;
__device__ __nv_bfloat16  g_embb[(NCC + 1) * DD];           // bf16 embedding
__device__ __nv_bfloat16  g_Wxb[4][(size_t)DD * HH];        // bf16 input weights

__device__ __forceinline__ float sigm(float v) { return 1.0f / (1.0f + expf(-v)); }

__device__ __forceinline__ void cp16(unsigned int dst, const void* src) {
    asm volatile("cp.async.cg.shared.global [%0], [%1], 16;\n" :: "r"(dst), "l"(src));
}
__device__ __forceinline__ void cp_commit() { asm volatile("cp.async.commit_group;\n"); }
template <int N> __device__ __forceinline__ void cp_wait() {
    asm volatile("cp.async.wait_group %0;\n" :: "n"(N));
}

// mbarrier helpers
__device__ __forceinline__ void mbar_init(unsigned mbar, unsigned cnt) {
    asm volatile("mbarrier.init.shared.b64 [%0], %1;" :: "r"(mbar), "r"(cnt) : "memory");
}
__device__ __forceinline__ void mbar_expect(unsigned mbar, unsigned bytes) {
    asm volatile("mbarrier.arrive.expect_tx.shared.b64 _, [%0], %1;" :: "r"(mbar), "r"(bytes) : "memory");
}
__device__ __forceinline__ void mbar_wait(unsigned mbar, unsigned phase) {
    asm volatile(
        "{\n\t.reg .pred P1;\n\t"
        "LAB_WAIT_%=:\n\t"
        "mbarrier.try_wait.parity.shared.b64 P1, [%0], %1;\n\t"
        "@P1 bra.uni DONE_%=;\n\t"
        "bra.uni LAB_WAIT_%=;\n\t"
        "DONE_%=:\n\t}"
        :: "r"(mbar), "r"(phase) : "memory");
}
__device__ __forceinline__ void bulk_g2s(unsigned dst, const void* src, unsigned bytes, unsigned mbar) {
    asm volatile("cp.async.bulk.shared::cluster.global.mbarrier::complete_tx::bytes [%0], [%1], %2, [%3];"
                 :: "r"(dst), "l"(src), "r"(bytes), "r"(mbar) : "memory");
}

// Sense-reversing grid barrier (atomic arrivals; last arrival releases) — R3-measured fast.
__device__ __forceinline__ void gridbar()
{
    __syncthreads();
    if (threadIdx.x == 0) {
        __threadfence();
        volatile unsigned* gen = &g_gen;
        unsigned g0 = *gen;
        unsigned arr = atomicAdd(&g_cnt, 1u);
        if (arr == NCTA_REC - 1) {
            g_cnt = 0;
            __threadfence();
            *gen = g0 + 1u;
        } else {
            while (*gen == g0) { }
        }
    }
    __syncthreads();
    __threadfence();
}

// ======================================================================
// Kernel 0: one-time f32 -> bf16 conversion of emb and the 4 input weights
// ======================================================================
__global__ __launch_bounds__(256) void k_convert(
    const float* __restrict__ emb,
    const float* __restrict__ W0, const float* __restrict__ W1,
    const float* __restrict__ W2, const float* __restrict__ W3)
{
    const float* Wsrc[4] = { W0, W1, W2, W3 };
    size_t tid    = (size_t)blockIdx.x * blockDim.x + threadIdx.x;
    size_t stride = (size_t)gridDim.x * blockDim.x;
    const size_t nW4 = (size_t)DD * HH / 4;
    for (size_t e = tid; e < 4 * nW4; e += stride) {
        int g = (int)(e / nW4);
        size_t o = (e % nW4) * 4;
        float4 v = *(const float4*)(Wsrc[g] + o);
        __nv_bfloat16* d = &g_Wxb[g][o];
        d[0] = __float2bfloat16(v.x); d[1] = __float2bfloat16(v.y);
        d[2] = __float2bfloat16(v.z); d[3] = __float2bfloat16(v.w);
    }
    const size_t nE4 = (size_t)(NCC + 1) * DD / 4;
    for (size_t e = tid; e < nE4; e += stride) {
        float4 v = *(const float4*)(emb + e * 4);
        __nv_bfloat16* d = &g_embb[e * 4];
        d[0] = __float2bfloat16(v.x); d[1] = __float2bfloat16(v.y);
        d[2] = __float2bfloat16(v.z); d[3] = __float2bfloat16(v.w);
    }
}

// ======================================================================
// Kernel 1: input projections (R3-measured double-buffered version)
// ======================================================================
#define AS_LD 56
#define BS_LD 152

__global__ __launch_bounds__(256) void k_input_proj(const int* __restrict__ x)
{
    __shared__ __align__(16) __nv_bfloat16 As[2][128 * AS_LD];
    __shared__ __align__(16) __nv_bfloat16 Bs[2][32 * BS_LD];
    __shared__ int rowidx[128];

    const int t = threadIdx.x, w = t >> 5;
    const int tn = blockIdx.x, tm = blockIdx.y;
    const int n0 = tn * 128, gate = n0 >> 10, h0 = n0 & 1023;
    const __nv_bfloat16* Wb = g_Wxb[gate];

    if (t < 128) {
        int m = tm * 128 + t;
        int s = m >> 7, b = m & 127;
        rowidx[t] = x[b * SS + s];
    }
    __syncthreads();

    auto issue = [&](int it) {
        int kt = it * 32;
        unsigned int Aa = (unsigned int)__cvta_generic_to_shared(As[it & 1]);
        unsigned int Ba = (unsigned int)__cvta_generic_to_shared(Bs[it & 1]);
#pragma unroll
        for (int i = 0; i < 2; i++) {
            int e = t + i * 256, r = e >> 2, seg = e & 3;
            cp16(Aa + (r * AS_LD + seg * 8) * 2,
                 g_embb + (size_t)rowidx[r] * DD + kt + seg * 8);
        }
#pragma unroll
        for (int i = 0; i < 2; i++) {
            int e = t + i * 256, r = e >> 4, seg = e & 15;
            cp16(Ba + (r * BS_LD + seg * 8) * 2,
                 Wb + (size_t)(kt + r) * HH + h0 + seg * 8);
        }
    };

    wmma::fragment<wmma::accumulator, 16, 16, 16, float> acc[8];
#pragma unroll
    for (int i = 0; i < 8; i++) wmma::fill_fragment(acc[i], 0.0f);

    issue(0); cp_commit();
    for (int it = 0; it < 16; it++) {
        if (it < 15) issue(it + 1);
        cp_commit();
        cp_wait<1>();
        __syncthreads();
        const __nv_bfloat16* A = As[it & 1];
        const __nv_bfloat16* B = Bs[it & 1];
#pragma unroll
        for (int ks = 0; ks < 2; ks++) {
            wmma::fragment<wmma::matrix_a, 16, 16, 16, __nv_bfloat16, wmma::row_major> af;
            wmma::load_matrix_sync(af, A + (w * 16) * AS_LD + ks * 16, AS_LD);
#pragma unroll
            for (int nb = 0; nb < 8; nb++) {
                wmma::fragment<wmma::matrix_b, 16, 16, 16, __nv_bfloat16, wmma::row_major> bfr;
                wmma::load_matrix_sync(bfr, B + (ks * 16) * BS_LD + nb * 16, BS_LD);
                wmma::mma_sync(acc[nb], af, bfr, acc[nb]);
            }
        }
        __syncthreads();
    }

    size_t base = (size_t)(tm * 128 + w * 16) * 4096 + n0;
#pragma unroll
    for (int nb = 0; nb < 8; nb++)
        wmma::store_matrix_sync(g_P + base + nb * 16, acc[nb], 4096, wmma::mem_row_major);
}

// ======================================================================
// Kernel 2: persistent recurrent scan with bulk-copied transposed h.
//  - h stored [u][b] bf16 with XOR swizzle baked into the global layout
//  - per step: 4 x 64KB cp.async.bulk chunks (2 SMEM buffers + mbarriers)
//  - inner GEMM: ldmatrix.x4.trans (A) + ldmatrix.x4 (B) + mma.m16n8k16
// ======================================================================
#define WS_LD 1032
#define CHUNK_BYTES 65536

// dyn smem layout (bytes)
#define SM_MBAR   0
#define SM_ABUF   128
#define SM_WS     (SM_ABUF + 2 * CHUNK_BYTES)        // 131200
#define SM_SG     (SM_WS + 32 * WS_LD * 2)           // 197248
#define SM_TOTAL  (SM_SG + 128 * 36 * 4)             // 215680

__global__ void __launch_bounds__(256, 1) k_recur(
    const int*   __restrict__ x,
    const float* __restrict__ Wfh, const float* __restrict__ Wih,
    const float* __restrict__ Wgh, const float* __restrict__ Woh,
    const float* __restrict__ bfp, const float* __restrict__ bip,
    const float* __restrict__ bgp, const float* __restrict__ bop)
{
    extern __shared__ __align__(128) unsigned char dyn[];
    __nv_bfloat16* Ws = (__nv_bfloat16*)(dyn + SM_WS);
    float*         Sg = (float*)(dyn + SM_SG);

    const unsigned smem0 = (unsigned)__cvta_generic_to_shared(dyn);
    const unsigned mb[2] = { smem0 + SM_MBAR, smem0 + SM_MBAR + 8 };
    const unsigned Abuf[2] = { smem0 + SM_ABUF, smem0 + SM_ABUF + CHUNK_BYTES };

    const int t = threadIdx.x, w = t >> 5, l = t & 31;
    const int c = blockIdx.x, u0 = c * 8;
    const float* Wg[4] = { Wfh, Wih, Wgh, Woh };

    if (t == 0) { mbar_init(mb[0], 1); mbar_init(mb[1], 1); }
    asm volatile("fence.proxy.async.shared::cta;" ::: "memory");

    // weight slice -> SMEM (bf16, n-major rows of k, stride WS_LD)
    for (int e = t; e < 32 * 1024; e += 256) {
        int k = e >> 5, col = e & 31, g = col >> 3, j = col & 7;
        Ws[col * WS_LD + k] = __float2bfloat16(Wg[g][(size_t)k * HH + u0 + j]);
    }
    // zero own 8 rows of hT buffer 0 (read at s=0)
    *(unsigned long long*)(g_hT2[0] + (u0 + (t >> 5)) * 256 + (t & 31) * 8) = 0ull;

    // epilogue thread mapping: b = t>>1, units u0+jq..u0+jq+3
    const int eb = t >> 1, jq = (t & 1) * 4;
    const float4 bias0 = *(const float4*)(bfp + u0 + jq);
    const float4 bias1 = *(const float4*)(bip + u0 + jq);
    const float4 bias2 = *(const float4*)(bgp + u0 + jq);
    const float4 bias3 = *(const float4*)(bop + u0 + jq);
    float C0 = 0.f, C1 = 0.f, C2 = 0.f, C3 = 0.f;   // cell state in registers

    // ldmatrix lane constants
    const unsigned a_sw   = (((unsigned)(2 * w + ((l >> 3) & 1)) ^ (unsigned)(l & 7)) << 4);
    const int      a_krow = (l & 7) + ((l >> 4) & 1) * 8;
    const unsigned WsA    = smem0 + SM_WS;
    const unsigned bbase  = WsA + ((l & 7) + ((l >> 4) & 1) * 8) * (WS_LD * 2) + ((l >> 3) & 1) * 16;

    __syncthreads();
    gridbar();   // zeros + mbarriers ready everywhere

    for (int s = 0; s < SS; s++) {
        const unsigned char* hsrc = g_hT2[s & 1];
        unsigned char*       hdst = g_hT2[(s + 1) & 1];

        if (t == 0) {
            mbar_expect(mb[0], CHUNK_BYTES);
            bulk_g2s(Abuf[0], hsrc + 0 * CHUNK_BYTES, CHUNK_BYTES, mb[0]);
            mbar_expect(mb[1], CHUNK_BYTES);
            bulk_g2s(Abuf[1], hsrc + 1 * CHUNK_BYTES, CHUNK_BYTES, mb[1]);
        }

        // prefetch input-side preacts + reset mask (independent of h)
        const float* Pb = g_P + ((size_t)(s * BB + eb)) * 4096 + (u0 + jq);
        float4 pf0 = *(const float4*)(Pb);
        float4 pf1 = *(const float4*)(Pb + 1024);
        float4 pf2 = *(const float4*)(Pb + 2048);
        float4 pf3 = *(const float4*)(Pb + 3072);
        const float rmask = (x[eb * SS + s] > 0) ? 1.0f : 0.0f;

        float acc[16];
#pragma unroll
        for (int i = 0; i < 16; i++) acc[i] = 0.0f;

        for (int kc = 0; kc < 4; kc++) {
            mbar_wait(mb[kc & 1], (kc >> 1) & 1);
            const unsigned Ab = Abuf[kc & 1];
#pragma unroll
            for (int kt = 0; kt < 16; kt++) {
                unsigned aaddr = Ab + (unsigned)((kt * 16 + a_krow) * 256) + a_sw;
                unsigned a0, a1, a2, a3;
                asm volatile("ldmatrix.sync.aligned.m8n8.x4.trans.shared.b16 {%0,%1,%2,%3}, [%4];"
                             : "=r"(a0), "=r"(a1), "=r"(a2), "=r"(a3) : "r"(aaddr));
                unsigned baddr = bbase + (unsigned)((kc * 16 + kt) * 32);
                unsigned b0, b1, b2, b3;
                asm volatile("ldmatrix.sync.aligned.m8n8.x4.shared.b16 {%0,%1,%2,%3}, [%4];"
                             : "=r"(b0), "=r"(b1), "=r"(b2), "=r"(b3) : "r"(baddr));
                asm volatile("mma.sync.aligned.m16n8k16.row.col.f32.bf16.bf16.f32 "
                             "{%0,%1,%2,%3}, {%4,%5,%6,%7}, {%8,%9}, {%0,%1,%2,%3};"
                             : "+f"(acc[0]), "+f"(acc[1]), "+f"(acc[2]), "+f"(acc[3])
                             : "r"(a0), "r"(a1), "r"(a2), "r"(a3), "r"(b0), "r"(b1));
                asm volatile("mma.sync.aligned.m16n8k16.row.col.f32.bf16.bf16.f32 "
                             "{%0,%1,%2,%3}, {%4,%5,%6,%7}, {%8,%9}, {%0,%1,%2,%3};"
                             : "+f"(acc[4]), "+f"(acc[5]), "+f"(acc[6]), "+f"(acc[7])
                             : "r"(a0), "r"(a1), "r"(a2), "r"(a3), "r"(b2), "r"(b3));
                unsigned baddr2 = baddr + 16u * (WS_LD * 2);
                asm volatile("ldmatrix.sync.aligned.m8n8.x4.shared.b16 {%0,%1,%2,%3}, [%4];"
                             : "=r"(b0), "=r"(b1), "=r"(b2), "=r"(b3) : "r"(baddr2));
                asm volatile("mma.sync.aligned.m16n8k16.row.col.f32.bf16.bf16.f32 "
                             "{%0,%1,%2,%3}, {%4,%5,%6,%7}, {%8,%9}, {%0,%1,%2,%3};"
                             : "+f"(acc[8]), "+f"(acc[9]), "+f"(acc[10]), "+f"(acc[11])
                             : "r"(a0), "r"(a1), "r"(a2), "r"(a3), "r"(b0), "r"(b1));
                asm volatile("mma.sync.aligned.m16n8k16.row.col.f32.bf16.bf16.f32 "
                             "{%0,%1,%2,%3}, {%4,%5,%6,%7}, {%8,%9}, {%0,%1,%2,%3};"
                             : "+f"(acc[12]), "+f"(acc[13]), "+f"(acc[14]), "+f"(acc[15])
                             : "r"(a0), "r"(a1), "r"(a2), "r"(a3), "r"(b2), "r"(b3));
            }
            __syncthreads();   // all warps done reading this buffer
            if (t == 0 && kc < 2) {
                mbar_expect(mb[kc & 1], CHUNK_BYTES);
                bulk_g2s(Abuf[kc & 1], hsrc + (kc + 2) * CHUNK_BYTES, CHUNK_BYTES, mb[kc & 1]);
            }
        }

        // store C-fragments to Sg [128 m][36 stride]
        {
            int mr = w * 16 + (l >> 2);
            int col = 2 * (l & 3);
#pragma unroll
            for (int nt = 0; nt < 4; nt++) {
                *(float2*)&Sg[mr * 36 + nt * 8 + col]       = make_float2(acc[nt * 4 + 0], acc[nt * 4 + 1]);
                *(float2*)&Sg[(mr + 8) * 36 + nt * 8 + col] = make_float2(acc[nt * 4 + 2], acc[nt * 4 + 3]);
            }
        }
        __syncthreads();

        // gate epilogue: thread handles (b=eb, units u0+jq..+3)
        {
            float4 S0 = *(float4*)&Sg[eb * 36 +  0 + jq];
            float4 S1 = *(float4*)&Sg[eb * 36 +  8 + jq];
            float4 S2 = *(float4*)&Sg[eb * 36 + 16 + jq];
            float4 S3 = *(float4*)&Sg[eb * 36 + 24 + jq];

            float f0 = sigm(pf0.x + bias0.x + S0.x), f1 = sigm(pf0.y + bias0.y + S0.y);
            float f2 = sigm(pf0.z + bias0.z + S0.z), f3 = sigm(pf0.w + bias0.w + S0.w);
            float i0 = sigm(pf1.x + bias1.x + S1.x), i1 = sigm(pf1.y + bias1.y + S1.y);
            float i2 = sigm(pf1.z + bias1.z + S1.z), i3 = sigm(pf1.w + bias1.w + S1.w);
            float g0 = sigm(pf2.x + bias2.x + S2.x), g1 = sigm(pf2.y + bias2.y + S2.y);
            float g2 = sigm(pf2.z + bias2.z + S2.z), g3 = sigm(pf2.w + bias2.w + S2.w);
            float o0 = sigm(pf3.x + bias3.x + S3.x), o1 = sigm(pf3.y + bias3.y + S3.y);
            float o2 = sigm(pf3.z + bias3.z + S3.z), o3 = sigm(pf3.w + bias3.w + S3.w);

            C0 = (g0 * i0 + C0 * f0) * rmask;
            C1 = (g1 * i1 + C1 * f1) * rmask;
            C2 = (g2 * i2 + C2 * f2) * rmask;
            C3 = (g3 * i3 + C3 * f3) * rmask;
            float h0v = o0 * tanhf(C0), h1v = o1 * tanhf(C1);
            float h2v = o2 * tanhf(C2), h3v = o3 * tanhf(C3);

            // swizzled transposed store: byte = u*256 + ((b>>3)^(u&7))*16 + (b&7)*2
            const unsigned blo = (unsigned)(eb & 7) * 2, bhi = (unsigned)(eb >> 3);
#pragma unroll
            for (int i = 0; i < 4; i++) {
                float hv = (i == 0) ? h0v : (i == 1) ? h1v : (i == 2) ? h2v : h3v;
                unsigned u = (unsigned)(u0 + jq + i);
                *(__nv_bfloat16*)(hdst + u * 256 + ((bhi ^ (u & 7)) << 4) + blo) = __float2bfloat16(hv);
                if (s == SS - 1) g_hf[eb * HH + u] = hv;
            }
        }

        if (s < SS - 1) gridbar();
    }
}

// ======================================================================
// Kernel 3: logits + log_softmax (256 thr, split-K x2, 4 accums)
// ======================================================================
__global__ __launch_bounds__(256) void k_final(
    const float* __restrict__ Wph, const float* __restrict__ bp,
    float* __restrict__ out)
{
    __shared__ float h[HH];
    __shared__ float part[NCC];
    __shared__ float red[NCC];
    const int b = blockIdx.x, t = threadIdx.x;
    const int cls = t & 127, half = t >> 7;

    for (int i = t; i < HH; i += 256) h[i] = g_hf[b * HH + i];
    __syncthreads();

    const float* W = Wph + (size_t)(half * 512) * NCC + cls;
    const float* hh = h + half * 512;
    float a0 = 0.f, a1 = 0.f, a2 = 0.f, a3 = 0.f;
#pragma unroll 8
    for (int k = 0; k < 512; k += 4) {
        a0 += hh[k + 0] * W[(size_t)(k + 0) * NCC];
        a1 += hh[k + 1] * W[(size_t)(k + 1) * NCC];
        a2 += hh[k + 2] * W[(size_t)(k + 2) * NCC];
        a3 += hh[k + 3] * W[(size_t)(k + 3) * NCC];
    }
    float p = (a0 + a1) + (a2 + a3);
    if (half) part[cls] = p;
    __syncthreads();

    if (half == 0) p += part[cls] + bp[cls];

    if (t < 128) red[t] = p;
    __syncthreads();
    for (int off = 64; off; off >>= 1) {
        if (t < off) red[t] = fmaxf(red[t], red[t + off]);
        __syncthreads();
    }
    float m = red[0]; __syncthreads();
    if (t < 128) red[t] = expf(p - m);
    __syncthreads();
    for (int off = 64; off; off >>= 1) {
        if (t < off) red[t] += red[t + off];
        __syncthreads();
    }
    if (t < 128) {
        float lse = m + logf(red[0]);
        out[b * NCC + t] = p - lse;
    }
}

// ======================================================================
extern "C" void kernel_launch(void* const* d_in, const int* in_sizes, int n_in,
                              void* d_out, int out_size)
{
    const int*   x   = (const int*)  d_in[0];
    const float* emb = (const float*)d_in[1];
    const float* Wfx = (const float*)d_in[2];
    const float* Wfh = (const float*)d_in[3];
    const float* bf  = (const float*)d_in[4];
    const float* Wix = (const float*)d_in[5];
    const float* Wih = (const float*)d_in[6];
    const float* bi  = (const float*)d_in[7];
    const float* Wgx = (const float*)d_in[8];
    const float* Wgh = (const float*)d_in[9];
    const float* bg  = (const float*)d_in[10];
    const float* Wox = (const float*)d_in[11];
    const float* Woh = (const float*)d_in[12];
    const float* bo  = (const float*)d_in[13];
    const float* Wph = (const float*)d_in[14];
    const float* bp  = (const float*)d_in[15];
    float* out = (float*)d_out;

    static bool attr_set = false;
    if (!attr_set) {
        cudaFuncSetAttribute(k_recur, cudaFuncAttributeMaxDynamicSharedMemorySize, SM_TOTAL);
        attr_set = true;
    }

    // 0) bf16 pre-conversion
    k_convert<<<512, 256>>>(emb, Wfx, Wix, Wgx, Wox);

    // 1) input-side projections
    dim3 g1(4096 / 128, (SS * BB) / 128);
    k_input_proj<<<g1, 256>>>(x);

    // 2) persistent recurrent scan
    k_recur<<<NCTA_REC, 256, SM_TOTAL>>>(x, Wfh, Wih, Wgh, Woh, bf, bi, bg, bo);

    // 3) final projection + log_softmax
    k_final<<<BB, 256>>>(Wph, bp, out);
}